// round 15
// baseline (speedup 1.0000x reference)
#include <cuda_runtime.h>
#include <cuda_fp16.h>
#include <math.h>
#include <stdint.h>

#define S_LEN 2048
#define D_MODEL 2048
#define N_HEADS 16
#define HD 128
#define E3 (3 * D_MODEL)   // 6144

// softmax scale folded with log2(e): softmax(s*scale) == exp2-softmax(s*scale*log2e)
#define SCALE_LOG2E (0.08838834764831845f * 1.4426950408889634f)

// ---------------- scratch (static device globals; no allocations) -------------
__device__ __half g_x16[(size_t)S_LEN * D_MODEL];
__device__ __half g_wq16[(size_t)E3 * D_MODEL];
__device__ __half g_wo16[(size_t)D_MODEL * D_MODEL];
__device__ __half g_q16[(size_t)S_LEN * D_MODEL];    // rope'd, pre-scaled by SCALE_LOG2E
__device__ __half g_k16[(size_t)S_LEN * D_MODEL];    // rope'd
__device__ __half g_vt16[(size_t)D_MODEL * S_LEN];   // V transposed: [hd_global][s]
__device__ __half g_at16[(size_t)S_LEN * D_MODEL];   // attention output fp16
__device__ float2 g_rope[(size_t)S_LEN * 64];        // (cos, sin) per (s, j)

// =============================================================================
// helpers (base-ISA only: mma.sync / ldmatrix / cp.async)
// =============================================================================
__device__ __forceinline__ uint32_t smem_u32(const void* p) {
    uint32_t a;
    asm("{ .reg .u64 t; cvta.to.shared.u64 t, %1; cvt.u32.u64 %0, t; }" : "=r"(a) : "l"(p));
    return a;
}
__device__ __forceinline__ void cp16(uint32_t dst, const void* src) {
    asm volatile("cp.async.cg.shared.global [%0], [%1], 16;" :: "r"(dst), "l"(src));
}
#define CP_COMMIT() asm volatile("cp.async.commit_group;" ::: "memory")
#define CP_WAIT(n)  asm volatile("cp.async.wait_group %0;" :: "n"(n) : "memory")

__device__ __forceinline__ void ldm4(uint32_t* r, uint32_t addr) {
    asm volatile("ldmatrix.sync.aligned.m8n8.x4.shared.b16 {%0,%1,%2,%3}, [%4];"
                 : "=r"(r[0]), "=r"(r[1]), "=r"(r[2]), "=r"(r[3]) : "r"(addr));
}
__device__ __forceinline__ void mma16816h(float* d, const uint32_t* a, uint32_t b0, uint32_t b1) {
    asm volatile(
        "mma.sync.aligned.m16n8k16.row.col.f32.f16.f16.f32 "
        "{%0,%1,%2,%3}, {%4,%5,%6,%7}, {%8,%9}, {%0,%1,%2,%3};"
        : "+f"(d[0]), "+f"(d[1]), "+f"(d[2]), "+f"(d[3])
        : "r"(a[0]), "r"(a[1]), "r"(a[2]), "r"(a[3]), "r"(b0), "r"(b1));
}
__device__ __forceinline__ uint32_t h2pack(float a, float b) {
    __half2 h = __floats2half2_rn(a, b);
    return *(uint32_t*)&h;
}

// =============================================================================
// shared GEMM mainloop config: CTA tile 128x256, K-tile 64, 4-stage cp.async,
// 256 threads, 8 warps as 2(m) x 4(n), warp tile 64x64.
// =============================================================================
#define TILE_A_B 16384               // A: 128 rows * 128B
#define TILE_B_B 32768               // B: 256 rows * 128B
#define STAGE_B (TILE_A_B + TILE_B_B)
#define NSTAGE 4
#define GEMM_SMEM (NSTAGE * STAGE_B) // 192 KB

// mainloop as a macro-like inline: computes acc[4][8][4] for (m0, n0)
#define GEMM_MAINLOOP(A_, B_, K_, lda_, ldb_)                                   \
    const int nt = (K_) / 64;                                                   \
    auto load_stage = [&](int t, int bufi) {                                    \
        const uint32_t base = sb + (uint32_t)bufi * STAGE_B;                    \
        _Pragma("unroll")                                                       \
        for (int i = 0; i < 4; i++) {                                           \
            const int cid = tid + 256 * i;                                      \
            const int row = cid >> 3;                                           \
            const int c   = cid & 7;                                            \
            const uint32_t phys = (uint32_t)(row * 128 + ((c ^ (row & 7)) << 4));\
            cp16(base + phys, (A_) + (size_t)(m0 + row) * (lda_) + (size_t)t * 64 + c * 8); \
        }                                                                       \
        _Pragma("unroll")                                                       \
        for (int i = 0; i < 8; i++) {                                           \
            const int cid = tid + 256 * i;                                      \
            const int row = cid >> 3;                                           \
            const int c   = cid & 7;                                            \
            const uint32_t phys = (uint32_t)(row * 128 + ((c ^ (row & 7)) << 4));\
            cp16(base + TILE_A_B + phys, (B_) + (size_t)(n0 + row) * (ldb_) + (size_t)t * 64 + c * 8); \
        }                                                                       \
        CP_COMMIT();                                                            \
    };                                                                          \
    load_stage(0, 0);                                                           \
    if (nt > 1) load_stage(1, 1);                                               \
    if (nt > 2) load_stage(2, 2);                                               \
    const int ar = wm * 64 + (lane & 15);                                       \
    const int br = wn * 64 + (lane & 15);                                       \
    int buf = 0;                                                                \
    for (int t = 0; t < nt; t++) {                                              \
        if (t + 1 < nt) {                                                       \
            if (t + 2 < nt) { CP_WAIT(2); } else { CP_WAIT(1); }                \
        } else {                                                                \
            CP_WAIT(0);                                                         \
        }                                                                       \
        __syncthreads();                                                        \
        if (t + 3 < nt) {                                                       \
            int nb_ = buf + 3; if (nb_ >= NSTAGE) nb_ -= NSTAGE;                \
            load_stage(t + 3, nb_);                                             \
        }                                                                       \
        const uint32_t tb = sb + (uint32_t)buf * STAGE_B;                       \
        _Pragma("unroll")                                                       \
        for (int k16 = 0; k16 < 4; k16++) {                                     \
            const int cb = k16 * 2 + (lane >> 4);                               \
            uint32_t af[4][4];                                                  \
            _Pragma("unroll")                                                   \
            for (int mb = 0; mb < 4; mb++) {                                    \
                const int R = ar + mb * 16;                                     \
                ldm4(af[mb], tb + (uint32_t)(R * 128 + ((cb ^ (R & 7)) << 4))); \
            }                                                                   \
            uint32_t bfr[4][4];                                                 \
            _Pragma("unroll")                                                   \
            for (int q = 0; q < 4; q++) {                                       \
                const int R = br + q * 16;                                      \
                ldm4(bfr[q], tb + TILE_A_B + (uint32_t)(R * 128 + ((cb ^ (R & 7)) << 4))); \
            }                                                                   \
            _Pragma("unroll")                                                   \
            for (int mb = 0; mb < 4; mb++)                                      \
                _Pragma("unroll")                                               \
                for (int q = 0; q < 4; q++) {                                   \
                    mma16816h(acc[mb][2 * q],     af[mb], bfr[q][0], bfr[q][2]);\
                    mma16816h(acc[mb][2 * q + 1], af[mb], bfr[q][1], bfr[q][3]);\
                }                                                               \
        }                                                                       \
        if (++buf == NSTAGE) buf = 0;                                           \
    }

// =============================================================================
// out-projection GEMM: fp32 C output
// =============================================================================
__global__ void __launch_bounds__(256, 1) gemm_tc_kernel(
    const __half* __restrict__ A, const __half* __restrict__ B,
    float* __restrict__ C,
    int K, int lda, int ldb, int ldc, float scale)
{
    extern __shared__ __align__(128) char smem[];
    const uint32_t sb = smem_u32(smem);
    const int tid = threadIdx.x;
    const int lane = tid & 31;
    const int wid = tid >> 5;
    const int wm = wid & 1;
    const int wn = wid >> 1;
    const int m0 = blockIdx.y * 128;
    const int n0 = blockIdx.x * 256;

    float acc[4][8][4];
#pragma unroll
    for (int a = 0; a < 4; a++)
#pragma unroll
        for (int b = 0; b < 8; b++)
#pragma unroll
            for (int c = 0; c < 4; c++) acc[a][b][c] = 0.0f;

    GEMM_MAINLOOP(A, B, K, lda, ldb)

    const int g  = lane >> 2;
    const int tg = lane & 3;
#pragma unroll
    for (int mb = 0; mb < 4; mb++) {
        const int row = m0 + wm * 64 + mb * 16 + g;
#pragma unroll
        for (int nb = 0; nb < 8; nb++) {
            const int col = n0 + wn * 64 + nb * 8 + tg * 2;
            float2 v0, v1;
            v0.x = acc[mb][nb][0] * scale; v0.y = acc[mb][nb][1] * scale;
            v1.x = acc[mb][nb][2] * scale; v1.y = acc[mb][nb][3] * scale;
            *(float2*)(C + (size_t)row * ldc + col)       = v0;
            *(float2*)(C + (size_t)(row + 8) * ldc + col) = v1;
        }
    }
}

// =============================================================================
// fused QKV GEMM: mainloop as above, epilogue stages the fp32 tile to smem and
// then applies RoPE (q/k regions, via precomputed table) or transpose (v),
// writing fp16 directly. Region by n0: [0,2048)=q, [2048,4096)=k, [4096,6144)=v.
// =============================================================================
#define FT_LD 261   // padded fp32 tile row stride (5 coprime 32 -> conflict-free cols)

__global__ void __launch_bounds__(256, 1) gemm_qkv_kernel(
    const __half* __restrict__ A, const __half* __restrict__ B,
    const float2* __restrict__ rope,
    __half* __restrict__ q16, __half* __restrict__ k16, __half* __restrict__ vt16)
{
    extern __shared__ __align__(128) char smem[];
    const uint32_t sb = smem_u32(smem);
    const int tid = threadIdx.x;
    const int lane = tid & 31;
    const int wid = tid >> 5;
    const int wm = wid & 1;
    const int wn = wid >> 1;
    const int m0 = blockIdx.y * 128;
    const int n0 = blockIdx.x * 256;

    float acc[4][8][4];
#pragma unroll
    for (int a = 0; a < 4; a++)
#pragma unroll
        for (int b = 0; b < 8; b++)
#pragma unroll
            for (int c = 0; c < 4; c++) acc[a][b][c] = 0.0f;

    GEMM_MAINLOOP(A, B, D_MODEL, D_MODEL, D_MODEL)

    // ---- stage fp32 tile to smem ----
    __syncthreads();   // all MMA smem reads done; safe to repurpose buffers
    float* ftile = (float*)smem;                 // [128][FT_LD]

    const int g  = lane >> 2;
    const int tg = lane & 3;
#pragma unroll
    for (int mb = 0; mb < 4; mb++) {
        const int row = wm * 64 + mb * 16 + g;
#pragma unroll
        for (int nb = 0; nb < 8; nb++) {
            const int col = wn * 64 + nb * 8 + tg * 2;
            ftile[row * FT_LD + col]           = acc[mb][nb][0];
            ftile[row * FT_LD + col + 1]       = acc[mb][nb][1];
            ftile[(row + 8) * FT_LD + col]     = acc[mb][nb][2];
            ftile[(row + 8) * FT_LD + col + 1] = acc[mb][nb][3];
        }
    }
    __syncthreads();

    const int region = n0 >> 11;   // 0=q, 1=k, 2=v
    if (region < 2) {
        __half* dst = (region == 0) ? q16 : k16;
        const float qs = (region == 0) ? SCALE_LOG2E : 1.0f;
        const int pc = tid & 127;          // pair-column 0..127
        const int hl = pc >> 6;            // head-local 0/1
        const int j  = pc & 63;
        const int rb = (tid >> 7) * 64;    // row base 0 or 64
        const int e_base = (n0 & 2047) + hl * 128;
        const float2* rp = rope + (size_t)(m0 + rb) * 64 + j;
        for (int r = 0; r < 64; r++) {
            const int row = rb + r;
            const int s   = m0 + row;
            const float v1 = ftile[row * FT_LD + hl * 128 + j];
            const float v2 = ftile[row * FT_LD + hl * 128 + j + 64];
            const float2 cssn = rp[(size_t)r * 64];
            dst[(size_t)s * D_MODEL + e_base + j]      = __float2half_rn((v1 * cssn.x - v2 * cssn.y) * qs);
            dst[(size_t)s * D_MODEL + e_base + j + 64] = __float2half_rn((v2 * cssn.x + v1 * cssn.y) * qs);
        }
    } else {
        // v region: transpose -> vt16[channel][s]
        const int e = tid;                 // local channel 0..255
        __half* vr = vt16 + (size_t)(n0 - 4096 + e) * S_LEN + m0;
#pragma unroll
        for (int k = 0; k < 16; k++) {
            __align__(16) __half tmp[8];
#pragma unroll
            for (int i = 0; i < 8; i++)
                tmp[i] = __float2half_rn(ftile[(8 * k + i) * FT_LD + e]);
            *(uint4*)(vr + 8 * k) = *(uint4*)tmp;
        }
    }
}

// =============================================================================
// rope table: identical math to the previous inline path (double pow + sincosf)
// =============================================================================
__global__ void __launch_bounds__(256) rope_tab_kernel(float2* __restrict__ tab)
{
    const int idx = blockIdx.x * 256 + threadIdx.x;    // 0..131071
    const int s = idx >> 6;
    const int j = idx & 63;
    const double inv = pow(10000.0, -(double)(2 * j) / 128.0);
    const float ang = (float)((double)s * inv);
    float sn, cs;
    sincosf(ang, &sn, &cs);
    tab[idx] = make_float2(cs, sn);
}

// =============================================================================
// flash attention: one CTA = (head, 128-row q tile). (unchanged from R13)
// =============================================================================
#define FL_TILE_B 32768              // 128 * 256B
#define FL_Q_OFF 0
#define FL_S_OFF 32768
#define FL_STAGE_B (2 * FL_TILE_B)   // K tile + Vt tile
#define FL_NKV 16                    // 2048 / 128
#define FLASH_SMEM (FL_S_OFF + 3 * FL_STAGE_B)   // 32KB + 192KB = 224KB

__device__ __forceinline__ uint32_t fl_phys(int row, int c) {
    return (uint32_t)(row * 256 + ((c ^ ((row & 7) << 1)) << 4));
}

__global__ void __launch_bounds__(256, 1) flash_kernel(
    const __half* __restrict__ q16, const __half* __restrict__ k16,
    const __half* __restrict__ vt16, __half* __restrict__ at16)
{
    extern __shared__ __align__(128) char smem[];
    const uint32_t sb = smem_u32(smem);
    const int tid = threadIdx.x;
    const int lane = tid & 31;
    const int wid = tid >> 5;
    const int h = blockIdx.y;
    const int q0 = blockIdx.x * 128;

#pragma unroll
    for (int i = 0; i < 8; i++) {
        const int cid = tid + 256 * i;
        const int row = cid >> 4;
        const int c   = cid & 15;
        cp16(sb + FL_Q_OFF + fl_phys(row, c),
             q16 + (size_t)(q0 + row) * D_MODEL + h * HD + c * 8);
    }
    auto load_kv = [&](int j, int buf) {
        const uint32_t base = sb + FL_S_OFF + (uint32_t)buf * FL_STAGE_B;
#pragma unroll
        for (int i = 0; i < 8; i++) {
            const int cid = tid + 256 * i;
            const int row = cid >> 4;
            const int c   = cid & 15;
            cp16(base + fl_phys(row, c),
                 k16 + (size_t)(j * 128 + row) * D_MODEL + h * HD + c * 8);
            cp16(base + FL_TILE_B + fl_phys(row, c),
                 vt16 + (size_t)(h * HD + row) * S_LEN + j * 128 + c * 8);
        }
        CP_COMMIT();
    };
    load_kv(0, 0);
    load_kv(1, 1);

    float o[16][4];
#pragma unroll
    for (int i = 0; i < 16; i++)
#pragma unroll
        for (int c = 0; c < 4; c++) o[i][c] = 0.0f;
    float m0 = -INFINITY, m1 = -INFINITY, l0 = 0.0f, l1 = 0.0f;

    const int arow = wid * 16 + (lane & 15);
    const int nrow = lane & 15;

    CP_WAIT(1);
    __syncthreads();
    uint32_t qf[8][4];
#pragma unroll
    for (int kk = 0; kk < 8; kk++) {
        const int cb = kk * 2 + (lane >> 4);
        ldm4(qf[kk], sb + FL_Q_OFF + fl_phys(arow, cb));
    }

    for (int j = 0; j < FL_NKV; j++) {
        if (j + 1 < FL_NKV) { CP_WAIT(1); } else { CP_WAIT(0); }
        __syncthreads();
        if (j + 2 < FL_NKV) {
            int nb = j + 2; load_kv(nb, nb % 3);
        }
        const uint32_t kb = sb + FL_S_OFF + (uint32_t)(j % 3) * FL_STAGE_B;

        float s[16][4];
#pragma unroll
        for (int i = 0; i < 16; i++)
#pragma unroll
            for (int c = 0; c < 4; c++) s[i][c] = 0.0f;

#pragma unroll
        for (int kk = 0; kk < 8; kk++) {
            const int cb = kk * 2 + (lane >> 4);
            uint32_t bf[4];
#pragma unroll
            for (int t = 0; t < 8; t++) {
                ldm4(bf, kb + fl_phys(t * 16 + nrow, cb));
                mma16816h(s[2 * t],     qf[kk], bf[0], bf[2]);
                mma16816h(s[2 * t + 1], qf[kk], bf[1], bf[3]);
            }
        }

        float mj0 = -INFINITY, mj1 = -INFINITY;
#pragma unroll
        for (int i = 0; i < 16; i++) {
            mj0 = fmaxf(mj0, fmaxf(s[i][0], s[i][1]));
            mj1 = fmaxf(mj1, fmaxf(s[i][2], s[i][3]));
        }
        mj0 = fmaxf(mj0, __shfl_xor_sync(0xffffffffu, mj0, 1));
        mj0 = fmaxf(mj0, __shfl_xor_sync(0xffffffffu, mj0, 2));
        mj1 = fmaxf(mj1, __shfl_xor_sync(0xffffffffu, mj1, 1));
        mj1 = fmaxf(mj1, __shfl_xor_sync(0xffffffffu, mj1, 2));
        const float mn0 = fmaxf(m0, mj0);
        const float mn1 = fmaxf(m1, mj1);
        const float a0 = exp2f(m0 - mn0);
        const float a1 = exp2f(m1 - mn1);
        m0 = mn0; m1 = mn1;

        float sum0 = 0.0f, sum1 = 0.0f;
        uint32_t pa[8][4];
#pragma unroll
        for (int t = 0; t < 8; t++) {
            const float e00 = exp2f(s[2 * t][0] - m0),     e01 = exp2f(s[2 * t][1] - m0);
            const float e02 = exp2f(s[2 * t][2] - m1),     e03 = exp2f(s[2 * t][3] - m1);
            const float e10 = exp2f(s[2 * t + 1][0] - m0), e11 = exp2f(s[2 * t + 1][1] - m0);
            const float e12 = exp2f(s[2 * t + 1][2] - m1), e13 = exp2f(s[2 * t + 1][3] - m1);
            sum0 += (e00 + e01) + (e10 + e11);
            sum1 += (e02 + e03) + (e12 + e13);
            pa[t][0] = h2pack(e00, e01);
            pa[t][1] = h2pack(e02, e03);
            pa[t][2] = h2pack(e10, e11);
            pa[t][3] = h2pack(e12, e13);
        }
        sum0 += __shfl_xor_sync(0xffffffffu, sum0, 1);
        sum0 += __shfl_xor_sync(0xffffffffu, sum0, 2);
        sum1 += __shfl_xor_sync(0xffffffffu, sum1, 1);
        sum1 += __shfl_xor_sync(0xffffffffu, sum1, 2);
        l0 = l0 * a0 + sum0;
        l1 = l1 * a1 + sum1;
#pragma unroll
        for (int i = 0; i < 16; i++) {
            o[i][0] *= a0; o[i][1] *= a0;
            o[i][2] *= a1; o[i][3] *= a1;
        }

#pragma unroll
        for (int t = 0; t < 8; t++) {
            const int cbv = t * 2 + (lane >> 4);
            uint32_t vf[4];
#pragma unroll
            for (int u = 0; u < 8; u++) {
                ldm4(vf, kb + FL_TILE_B + fl_phys(u * 16 + nrow, cbv));
                mma16816h(o[2 * u],     pa[t], vf[0], vf[2]);
                mma16816h(o[2 * u + 1], pa[t], vf[1], vf[3]);
            }
        }
    }

    const int g  = lane >> 2;
    const int tg = lane & 3;
    const float r0 = 1.0f / l0;
    const float r1 = 1.0f / l1;
    const size_t row0 = (size_t)(q0 + wid * 16 + g) * D_MODEL + h * HD;
    const size_t row1 = row0 + (size_t)8 * D_MODEL;
#pragma unroll
    for (int nb = 0; nb < 16; nb++) {
        const int col = nb * 8 + tg * 2;
        *(uint32_t*)(at16 + row0 + col) = h2pack(o[nb][0] * r0, o[nb][1] * r0);
        *(uint32_t*)(at16 + row1 + col) = h2pack(o[nb][2] * r1, o[nb][3] * r1);
    }
}

// =============================================================================
// fused convert kernel: all three fp32 -> fp16 conversions in one launch
// =============================================================================
#define N4_X  ((long long)S_LEN * D_MODEL / 4)       // 1048576
#define N4_WQ ((long long)E3 * D_MODEL / 4)          // 3145728
#define N4_WO ((long long)D_MODEL * D_MODEL / 4)     // 1048576
#define N4_ALL (N4_X + N4_WQ + N4_WO)

__global__ void __launch_bounds__(256) cvt_all_kernel(
    const float* __restrict__ x,  __half* __restrict__ x16,
    const float* __restrict__ wq, __half* __restrict__ wq16,
    const float* __restrict__ wo, __half* __restrict__ wo16)
{
    long long i = (long long)blockIdx.x * 256 + threadIdx.x;
    const float* src;
    __half* dst;
    if (i < N4_X) {
        src = x; dst = x16;
    } else if (i < N4_X + N4_WQ) {
        i -= N4_X; src = wq; dst = wq16;
    } else {
        i -= N4_X + N4_WQ; src = wo; dst = wo16;
    }
    float4 v = ((const float4*)src)[i];
    uint2 o;
    o.x = h2pack(v.x, v.y);
    o.y = h2pack(v.z, v.w);
    ((uint2*)dst)[i] = o;
}

// =============================================================================
// launch
// =============================================================================
extern "C" void kernel_launch(void* const* d_in, const int* in_sizes, int n_in,
                              void* d_out, int out_size)
{
    (void)in_sizes; (void)n_in; (void)out_size;
    const float* x     = (const float*)d_in[0];   // [1, 2048, 2048]
    const float* w_qkv = (const float*)d_in[1];   // [6144, 2048]
    const float* w_out = (const float*)d_in[2];   // [2048, 2048]
    float* out = (float*)d_out;                   // [1, 2048, 2048]

    __half *x16, *wq16, *wo16, *q16, *k16, *vt16, *at16;
    float2* rope;
    cudaGetSymbolAddress((void**)&x16,  g_x16);
    cudaGetSymbolAddress((void**)&wq16, g_wq16);
    cudaGetSymbolAddress((void**)&wo16, g_wo16);
    cudaGetSymbolAddress((void**)&q16,  g_q16);
    cudaGetSymbolAddress((void**)&k16,  g_k16);
    cudaGetSymbolAddress((void**)&vt16, g_vt16);
    cudaGetSymbolAddress((void**)&at16, g_at16);
    cudaGetSymbolAddress((void**)&rope, g_rope);

    cudaFuncSetAttribute(gemm_tc_kernel,  cudaFuncAttributeMaxDynamicSharedMemorySize, GEMM_SMEM);
    cudaFuncSetAttribute(gemm_qkv_kernel, cudaFuncAttributeMaxDynamicSharedMemorySize, GEMM_SMEM);
    cudaFuncSetAttribute(flash_kernel,    cudaFuncAttributeMaxDynamicSharedMemorySize, FLASH_SMEM);

    // 0) rope table + fused fp32->fp16 conversions
    rope_tab_kernel<<<(S_LEN * 64) / 256, 256>>>(rope);
    cvt_all_kernel<<<(unsigned)((N4_ALL + 255) / 256), 256>>>(x, x16, w_qkv, wq16, w_out, wo16);

    // 1) fused QKV projection + RoPE + V transpose -> q16, k16, vt16
    {
        dim3 grid(E3 / 256, S_LEN / 128, 1);
        gemm_qkv_kernel<<<grid, 256, GEMM_SMEM>>>(x16, wq16, rope, q16, k16, vt16);
    }

    // 2) flash attention: scores + softmax + PV fused -> at16
    {
        dim3 grid(S_LEN / 128, N_HEADS, 1);
        flash_kernel<<<grid, 256, FLASH_SMEM>>>(q16, k16, vt16, at16);
    }

    // 3) out projection (fp32 out)
    {
        dim3 grid(D_MODEL / 256, S_LEN / 128, 1);
        gemm_tc_kernel<<<grid, 256, GEMM_SMEM>>>(at16, wo16, out,
                                                 D_MODEL, D_MODEL, D_MODEL, D_MODEL, 1.0f);
    }
}

// round 16
// speedup vs baseline: 1.0528x; 1.0528x over previous
#include <cuda_runtime.h>
#include <cuda_fp16.h>
#include <math.h>
#include <stdint.h>

#define S_LEN 2048
#define D_MODEL 2048
#define N_HEADS 16
#define HD 128
#define E3 (3 * D_MODEL)   // 6144

// softmax scale folded with log2(e): softmax(s*scale) == exp2-softmax(s*scale*log2e)
#define SCALE_LOG2E (0.08838834764831845f * 1.4426950408889634f)

// ---------------- scratch (static device globals; no allocations) -------------
__device__ __half g_x16[(size_t)S_LEN * D_MODEL];
__device__ __half g_wq16[(size_t)E3 * D_MODEL];
__device__ __half g_wo16[(size_t)D_MODEL * D_MODEL];
__device__ __half g_q16[(size_t)S_LEN * D_MODEL];    // rope'd, pre-scaled by SCALE_LOG2E
__device__ __half g_k16[(size_t)S_LEN * D_MODEL];    // rope'd
__device__ __half g_vt16[(size_t)D_MODEL * S_LEN];   // V transposed: [hd_global][s]
__device__ __half g_at16[(size_t)S_LEN * D_MODEL];   // attention output fp16
__device__ float2 g_rope[(size_t)S_LEN * 64];        // (cos, sin) per (s, j)

// =============================================================================
// helpers (base-ISA only: mma.sync / ldmatrix / cp.async)
// =============================================================================
__device__ __forceinline__ uint32_t smem_u32(const void* p) {
    uint32_t a;
    asm("{ .reg .u64 t; cvta.to.shared.u64 t, %1; cvt.u32.u64 %0, t; }" : "=r"(a) : "l"(p));
    return a;
}
__device__ __forceinline__ void cp16(uint32_t dst, const void* src) {
    asm volatile("cp.async.cg.shared.global [%0], [%1], 16;" :: "r"(dst), "l"(src));
}
#define CP_COMMIT() asm volatile("cp.async.commit_group;" ::: "memory")
#define CP_WAIT(n)  asm volatile("cp.async.wait_group %0;" :: "n"(n) : "memory")

__device__ __forceinline__ void ldm4(uint32_t* r, uint32_t addr) {
    asm volatile("ldmatrix.sync.aligned.m8n8.x4.shared.b16 {%0,%1,%2,%3}, [%4];"
                 : "=r"(r[0]), "=r"(r[1]), "=r"(r[2]), "=r"(r[3]) : "r"(addr));
}
__device__ __forceinline__ void mma16816h(float* d, const uint32_t* a, uint32_t b0, uint32_t b1) {
    asm volatile(
        "mma.sync.aligned.m16n8k16.row.col.f32.f16.f16.f32 "
        "{%0,%1,%2,%3}, {%4,%5,%6,%7}, {%8,%9}, {%0,%1,%2,%3};"
        : "+f"(d[0]), "+f"(d[1]), "+f"(d[2]), "+f"(d[3])
        : "r"(a[0]), "r"(a[1]), "r"(a[2]), "r"(a[3]), "r"(b0), "r"(b1));
}
__device__ __forceinline__ uint32_t h2pack(float a, float b) {
    __half2 h = __floats2half2_rn(a, b);
    return *(uint32_t*)&h;
}

// =============================================================================
// shared GEMM mainloop config: CTA tile 128x256, K-tile 64, 4-stage cp.async,
// 256 threads, 8 warps as 2(m) x 4(n), warp tile 64x64.
// =============================================================================
#define TILE_A_B 16384               // A: 128 rows * 128B
#define TILE_B_B 32768               // B: 256 rows * 128B
#define STAGE_B (TILE_A_B + TILE_B_B)
#define NSTAGE 4
#define GEMM_SMEM (NSTAGE * STAGE_B) // 192 KB

// mainloop as a macro-like inline: computes acc[4][8][4] for (m0, n0)
#define GEMM_MAINLOOP(A_, B_, K_, lda_, ldb_)                                   \
    const int nt = (K_) / 64;                                                   \
    auto load_stage = [&](int t, int bufi) {                                    \
        const uint32_t base = sb + (uint32_t)bufi * STAGE_B;                    \
        _Pragma("unroll")                                                       \
        for (int i = 0; i < 4; i++) {                                           \
            const int cid = tid + 256 * i;                                      \
            const int row = cid >> 3;                                           \
            const int c   = cid & 7;                                            \
            const uint32_t phys = (uint32_t)(row * 128 + ((c ^ (row & 7)) << 4));\
            cp16(base + phys, (A_) + (size_t)(m0 + row) * (lda_) + (size_t)t * 64 + c * 8); \
        }                                                                       \
        _Pragma("unroll")                                                       \
        for (int i = 0; i < 8; i++) {                                           \
            const int cid = tid + 256 * i;                                      \
            const int row = cid >> 3;                                           \
            const int c   = cid & 7;                                            \
            const uint32_t phys = (uint32_t)(row * 128 + ((c ^ (row & 7)) << 4));\
            cp16(base + TILE_A_B + phys, (B_) + (size_t)(n0 + row) * (ldb_) + (size_t)t * 64 + c * 8); \
        }                                                                       \
        CP_COMMIT();                                                            \
    };                                                                          \
    load_stage(0, 0);                                                           \
    if (nt > 1) load_stage(1, 1);                                               \
    if (nt > 2) load_stage(2, 2);                                               \
    const int ar = wm * 64 + (lane & 15);                                       \
    const int br = wn * 64 + (lane & 15);                                       \
    int buf = 0;                                                                \
    for (int t = 0; t < nt; t++) {                                              \
        if (t + 1 < nt) {                                                       \
            if (t + 2 < nt) { CP_WAIT(2); } else { CP_WAIT(1); }                \
        } else {                                                                \
            CP_WAIT(0);                                                         \
        }                                                                       \
        __syncthreads();                                                        \
        if (t + 3 < nt) {                                                       \
            int nb_ = buf + 3; if (nb_ >= NSTAGE) nb_ -= NSTAGE;                \
            load_stage(t + 3, nb_);                                             \
        }                                                                       \
        const uint32_t tb = sb + (uint32_t)buf * STAGE_B;                       \
        _Pragma("unroll")                                                       \
        for (int k16 = 0; k16 < 4; k16++) {                                     \
            const int cb = k16 * 2 + (lane >> 4);                               \
            uint32_t af[4][4];                                                  \
            _Pragma("unroll")                                                   \
            for (int mb = 0; mb < 4; mb++) {                                    \
                const int R = ar + mb * 16;                                     \
                ldm4(af[mb], tb + (uint32_t)(R * 128 + ((cb ^ (R & 7)) << 4))); \
            }                                                                   \
            uint32_t bfr[4][4];                                                 \
            _Pragma("unroll")                                                   \
            for (int q = 0; q < 4; q++) {                                       \
                const int R = br + q * 16;                                      \
                ldm4(bfr[q], tb + TILE_A_B + (uint32_t)(R * 128 + ((cb ^ (R & 7)) << 4))); \
            }                                                                   \
            _Pragma("unroll")                                                   \
            for (int mb = 0; mb < 4; mb++)                                      \
                _Pragma("unroll")                                               \
                for (int q = 0; q < 4; q++) {                                   \
                    mma16816h(acc[mb][2 * q],     af[mb], bfr[q][0], bfr[q][2]);\
                    mma16816h(acc[mb][2 * q + 1], af[mb], bfr[q][1], bfr[q][3]);\
                }                                                               \
        }                                                                       \
        if (++buf == NSTAGE) buf = 0;                                           \
    }

// =============================================================================
// out-projection GEMM: fp32 C output
// =============================================================================
__global__ void __launch_bounds__(256, 1) gemm_tc_kernel(
    const __half* __restrict__ A, const __half* __restrict__ B,
    float* __restrict__ C,
    int K, int lda, int ldb, int ldc, float scale)
{
    extern __shared__ __align__(128) char smem[];
    const uint32_t sb = smem_u32(smem);
    const int tid = threadIdx.x;
    const int lane = tid & 31;
    const int wid = tid >> 5;
    const int wm = wid & 1;
    const int wn = wid >> 1;
    const int m0 = blockIdx.y * 128;
    const int n0 = blockIdx.x * 256;

    float acc[4][8][4];
#pragma unroll
    for (int a = 0; a < 4; a++)
#pragma unroll
        for (int b = 0; b < 8; b++)
#pragma unroll
            for (int c = 0; c < 4; c++) acc[a][b][c] = 0.0f;

    GEMM_MAINLOOP(A, B, K, lda, ldb)

    const int g  = lane >> 2;
    const int tg = lane & 3;
#pragma unroll
    for (int mb = 0; mb < 4; mb++) {
        const int row = m0 + wm * 64 + mb * 16 + g;
#pragma unroll
        for (int nb = 0; nb < 8; nb++) {
            const int col = n0 + wn * 64 + nb * 8 + tg * 2;
            float2 v0, v1;
            v0.x = acc[mb][nb][0] * scale; v0.y = acc[mb][nb][1] * scale;
            v1.x = acc[mb][nb][2] * scale; v1.y = acc[mb][nb][3] * scale;
            *(float2*)(C + (size_t)row * ldc + col)       = v0;
            *(float2*)(C + (size_t)(row + 8) * ldc + col) = v1;
        }
    }
}

// =============================================================================
// fused QKV GEMM: epilogue applies RoPE (table) or V-transpose, writes fp16.
// =============================================================================
#define FT_LD 261   // padded fp32 tile row stride

__global__ void __launch_bounds__(256, 1) gemm_qkv_kernel(
    const __half* __restrict__ A, const __half* __restrict__ B,
    const float2* __restrict__ rope,
    __half* __restrict__ q16, __half* __restrict__ k16, __half* __restrict__ vt16)
{
    extern __shared__ __align__(128) char smem[];
    const uint32_t sb = smem_u32(smem);
    const int tid = threadIdx.x;
    const int lane = tid & 31;
    const int wid = tid >> 5;
    const int wm = wid & 1;
    const int wn = wid >> 1;
    const int m0 = blockIdx.y * 128;
    const int n0 = blockIdx.x * 256;

    float acc[4][8][4];
#pragma unroll
    for (int a = 0; a < 4; a++)
#pragma unroll
        for (int b = 0; b < 8; b++)
#pragma unroll
            for (int c = 0; c < 4; c++) acc[a][b][c] = 0.0f;

    GEMM_MAINLOOP(A, B, D_MODEL, D_MODEL, D_MODEL)

    __syncthreads();
    float* ftile = (float*)smem;                 // [128][FT_LD]

    const int g  = lane >> 2;
    const int tg = lane & 3;
#pragma unroll
    for (int mb = 0; mb < 4; mb++) {
        const int row = wm * 64 + mb * 16 + g;
#pragma unroll
        for (int nb = 0; nb < 8; nb++) {
            const int col = wn * 64 + nb * 8 + tg * 2;
            ftile[row * FT_LD + col]           = acc[mb][nb][0];
            ftile[row * FT_LD + col + 1]       = acc[mb][nb][1];
            ftile[(row + 8) * FT_LD + col]     = acc[mb][nb][2];
            ftile[(row + 8) * FT_LD + col + 1] = acc[mb][nb][3];
        }
    }
    __syncthreads();

    const int region = n0 >> 11;   // 0=q, 1=k, 2=v
    if (region < 2) {
        __half* dst = (region == 0) ? q16 : k16;
        const float qs = (region == 0) ? SCALE_LOG2E : 1.0f;
        const int pc = tid & 127;
        const int hl = pc >> 6;
        const int j  = pc & 63;
        const int rb = (tid >> 7) * 64;
        const int e_base = (n0 & 2047) + hl * 128;
        const float2* rp = rope + (size_t)(m0 + rb) * 64 + j;
        for (int r = 0; r < 64; r++) {
            const int row = rb + r;
            const int s   = m0 + row;
            const float v1 = ftile[row * FT_LD + hl * 128 + j];
            const float v2 = ftile[row * FT_LD + hl * 128 + j + 64];
            const float2 cssn = rp[(size_t)r * 64];
            dst[(size_t)s * D_MODEL + e_base + j]      = __float2half_rn((v1 * cssn.x - v2 * cssn.y) * qs);
            dst[(size_t)s * D_MODEL + e_base + j + 64] = __float2half_rn((v2 * cssn.x + v1 * cssn.y) * qs);
        }
    } else {
        const int e = tid;
        __half* vr = vt16 + (size_t)(n0 - 4096 + e) * S_LEN + m0;
#pragma unroll
        for (int k = 0; k < 16; k++) {
            __align__(16) __half tmp[8];
#pragma unroll
            for (int i = 0; i < 8; i++)
                tmp[i] = __float2half_rn(ftile[(8 * k + i) * FT_LD + e]);
            *(uint4*)(vr + 8 * k) = *(uint4*)tmp;
        }
    }
}

// =============================================================================
// rope table
// =============================================================================
__global__ void __launch_bounds__(256) rope_tab_kernel(float2* __restrict__ tab)
{
    const int idx = blockIdx.x * 256 + threadIdx.x;
    const int s = idx >> 6;
    const int j = idx & 63;
    const double inv = pow(10000.0, -(double)(2 * j) / 128.0);
    const float ang = (float)((double)s * inv);
    float sn, cs;
    sincosf(ang, &sn, &cs);
    tab[idx] = make_float2(cs, sn);
}

// =============================================================================
// flash attention v2: one CTA = (head, 256-row q tile), 8 warps, warp = 32 q rows.
// KV blocks of 64; K-frag reuse x2 via two A-frags. Q tile resident in smem.
// grid = (2048/256, 16) = 128 CTAs -> single wave.
// smem: Q 64KB + 4 stages x (K 16KB + Vt 16KB) = 192KB.
// =============================================================================
#define FL_Q_B    65536              // 256 rows * 256B
#define FL_K_B    16384              // 64 rows * 256B
#define FL_ST_B   32768              // K + Vt
#define FL_NST    4
#define FL_NKV    32                 // 2048 / 64
#define FLASH_SMEM (FL_Q_B + FL_NST * FL_ST_B)   // 192KB

__device__ __forceinline__ uint32_t fl_phys(int row, int c) {    // 256B rows, c 0..15
    return (uint32_t)(row * 256 + ((c ^ ((row & 7) << 1)) << 4));
}
__device__ __forceinline__ uint32_t flv_phys(int row, int c) {   // 128B rows, c 0..7
    return (uint32_t)(row * 128 + ((c ^ (row & 7)) << 4));
}

__global__ void __launch_bounds__(256, 1) flash_kernel(
    const __half* __restrict__ q16, const __half* __restrict__ k16,
    const __half* __restrict__ vt16, __half* __restrict__ at16)
{
    extern __shared__ __align__(128) char smem[];
    const uint32_t sb = smem_u32(smem);
    const int tid = threadIdx.x;
    const int lane = tid & 31;
    const int wid = tid >> 5;
    const int head = blockIdx.y;
    const int q0 = blockIdx.x * 256;

    // ---- load Q tile (256 rows), part of cp.async group 0 ----
#pragma unroll
    for (int i = 0; i < 16; i++) {
        const int cid = tid + 256 * i;      // 0..4095
        const int row = cid >> 4;
        const int c   = cid & 15;
        cp16(sb + fl_phys(row, c),
             q16 + (size_t)(q0 + row) * D_MODEL + head * HD + c * 8);
    }
    auto load_kv = [&](int j, int buf) {
        const uint32_t base = sb + FL_Q_B + (uint32_t)buf * FL_ST_B;
#pragma unroll
        for (int i = 0; i < 4; i++) {       // K: 64 rows x 16 chunks
            const int cid = tid + 256 * i;  // 0..1023
            const int row = cid >> 4;
            const int c   = cid & 15;
            cp16(base + fl_phys(row, c),
                 k16 + (size_t)(j * 64 + row) * D_MODEL + head * HD + c * 8);
        }
#pragma unroll
        for (int i = 0; i < 4; i++) {       // Vt: 128 rows x 8 chunks (128B rows)
            const int cid = tid + 256 * i;
            const int row = cid >> 3;       // 0..127
            const int c   = cid & 7;
            cp16(base + FL_K_B + flv_phys(row, c),
                 vt16 + (size_t)(head * HD + row) * S_LEN + j * 64 + c * 8);
        }
        CP_COMMIT();
    };
    load_kv(0, 0);   // group 0 includes Q
    load_kv(1, 1);
    load_kv(2, 2);

    float o[2][16][4];
#pragma unroll
    for (int hh = 0; hh < 2; hh++)
#pragma unroll
        for (int i = 0; i < 16; i++)
#pragma unroll
            for (int c = 0; c < 4; c++) o[hh][i][c] = 0.0f;
    float mA[2] = {-INFINITY, -INFINITY}, mB[2] = {-INFINITY, -INFINITY};
    float lA[2] = {0.0f, 0.0f}, lB[2] = {0.0f, 0.0f};

    const int qr = wid * 32 + (lane & 15);
    const int nr = lane & 15;

    for (int j = 0; j < FL_NKV; j++) {
        if (j + 1 < FL_NKV) {
            if (j + 2 < FL_NKV) { CP_WAIT(2); } else { CP_WAIT(1); }
        } else {
            CP_WAIT(0);
        }
        __syncthreads();
        if (j + 3 < FL_NKV) load_kv(j + 3, (j + 3) & 3);
        const uint32_t kb = sb + FL_Q_B + (uint32_t)(j & 3) * FL_ST_B;

        // ---- S = Q·K^T : 32 q x 64 kv per warp, fp32 ----
        float s[2][8][4];
#pragma unroll
        for (int hh = 0; hh < 2; hh++)
#pragma unroll
            for (int i = 0; i < 8; i++)
#pragma unroll
                for (int c = 0; c < 4; c++) s[hh][i][c] = 0.0f;

#pragma unroll
        for (int kk = 0; kk < 8; kk++) {
            const int cb = kk * 2 + (lane >> 4);
            uint32_t q0f[4], q1f[4];
            ldm4(q0f, sb + fl_phys(qr, cb));
            ldm4(q1f, sb + fl_phys(qr + 16, cb));
            uint32_t bf[4];
#pragma unroll
            for (int t = 0; t < 4; t++) {
                ldm4(bf, kb + fl_phys(t * 16 + nr, cb));
                mma16816h(s[0][2 * t],     q0f, bf[0], bf[2]);
                mma16816h(s[0][2 * t + 1], q0f, bf[1], bf[3]);
                mma16816h(s[1][2 * t],     q1f, bf[0], bf[2]);
                mma16816h(s[1][2 * t + 1], q1f, bf[1], bf[3]);
            }
        }

        // ---- online softmax (exp2 space), per half ----
        float a_[2][2];
        uint32_t pa[2][4][4];
#pragma unroll
        for (int hh = 0; hh < 2; hh++) {
            float mjA = -INFINITY, mjB = -INFINITY;
#pragma unroll
            for (int i = 0; i < 8; i++) {
                mjA = fmaxf(mjA, fmaxf(s[hh][i][0], s[hh][i][1]));
                mjB = fmaxf(mjB, fmaxf(s[hh][i][2], s[hh][i][3]));
            }
            mjA = fmaxf(mjA, __shfl_xor_sync(0xffffffffu, mjA, 1));
            mjA = fmaxf(mjA, __shfl_xor_sync(0xffffffffu, mjA, 2));
            mjB = fmaxf(mjB, __shfl_xor_sync(0xffffffffu, mjB, 1));
            mjB = fmaxf(mjB, __shfl_xor_sync(0xffffffffu, mjB, 2));
            const float mnA = fmaxf(mA[hh], mjA);
            const float mnB = fmaxf(mB[hh], mjB);
            a_[hh][0] = exp2f(mA[hh] - mnA);
            a_[hh][1] = exp2f(mB[hh] - mnB);
            mA[hh] = mnA; mB[hh] = mnB;

            float sumA = 0.0f, sumB = 0.0f;
#pragma unroll
            for (int t = 0; t < 4; t++) {
                const float e00 = exp2f(s[hh][2 * t][0] - mnA),     e01 = exp2f(s[hh][2 * t][1] - mnA);
                const float e02 = exp2f(s[hh][2 * t][2] - mnB),     e03 = exp2f(s[hh][2 * t][3] - mnB);
                const float e10 = exp2f(s[hh][2 * t + 1][0] - mnA), e11 = exp2f(s[hh][2 * t + 1][1] - mnA);
                const float e12 = exp2f(s[hh][2 * t + 1][2] - mnB), e13 = exp2f(s[hh][2 * t + 1][3] - mnB);
                sumA += (e00 + e01) + (e10 + e11);
                sumB += (e02 + e03) + (e12 + e13);
                pa[hh][t][0] = h2pack(e00, e01);
                pa[hh][t][1] = h2pack(e02, e03);
                pa[hh][t][2] = h2pack(e10, e11);
                pa[hh][t][3] = h2pack(e12, e13);
            }
            sumA += __shfl_xor_sync(0xffffffffu, sumA, 1);
            sumA += __shfl_xor_sync(0xffffffffu, sumA, 2);
            sumB += __shfl_xor_sync(0xffffffffu, sumB, 1);
            sumB += __shfl_xor_sync(0xffffffffu, sumB, 2);
            lA[hh] = lA[hh] * a_[hh][0] + sumA;
            lB[hh] = lB[hh] * a_[hh][1] + sumB;
        }

        // rescale O only if any row's max changed (a == 1.0 exactly otherwise)
        const bool need = (a_[0][0] < 1.0f) | (a_[0][1] < 1.0f) |
                          (a_[1][0] < 1.0f) | (a_[1][1] < 1.0f);
        if (__any_sync(0xffffffffu, need)) {
#pragma unroll
            for (int hh = 0; hh < 2; hh++)
#pragma unroll
                for (int i = 0; i < 16; i++) {
                    o[hh][i][0] *= a_[hh][0]; o[hh][i][1] *= a_[hh][0];
                    o[hh][i][2] *= a_[hh][1]; o[hh][i][3] *= a_[hh][1];
                }
        }

        // ---- O += P·V ----
#pragma unroll
        for (int t = 0; t < 4; t++) {
            const int cbv = t * 2 + (lane >> 4);
            uint32_t vf[4];
#pragma unroll
            for (int u = 0; u < 8; u++) {
                ldm4(vf, kb + FL_K_B + flv_phys(u * 16 + nr, cbv));
                mma16816h(o[0][2 * u],     pa[0][t], vf[0], vf[2]);
                mma16816h(o[0][2 * u + 1], pa[0][t], vf[1], vf[3]);
                mma16816h(o[1][2 * u],     pa[1][t], vf[0], vf[2]);
                mma16816h(o[1][2 * u + 1], pa[1][t], vf[1], vf[3]);
            }
        }
    }

    // ---- epilogue: normalize and store fp16 ----
    const int g  = lane >> 2;
    const int tg = lane & 3;
#pragma unroll
    for (int hh = 0; hh < 2; hh++) {
        const float rA = 1.0f / lA[hh];
        const float rB = 1.0f / lB[hh];
        const size_t rowA = (size_t)(q0 + wid * 32 + hh * 16 + g) * D_MODEL + head * HD;
        const size_t rowB = rowA + (size_t)8 * D_MODEL;
#pragma unroll
        for (int nb = 0; nb < 16; nb++) {
            const int col = nb * 8 + tg * 2;
            *(uint32_t*)(at16 + rowA + col) = h2pack(o[hh][nb][0] * rA, o[hh][nb][1] * rA);
            *(uint32_t*)(at16 + rowB + col) = h2pack(o[hh][nb][2] * rB, o[hh][nb][3] * rB);
        }
    }
}

// =============================================================================
// fused convert kernel: all three fp32 -> fp16 conversions in one launch
// =============================================================================
#define N4_X  ((long long)S_LEN * D_MODEL / 4)
#define N4_WQ ((long long)E3 * D_MODEL / 4)
#define N4_WO ((long long)D_MODEL * D_MODEL / 4)
#define N4_ALL (N4_X + N4_WQ + N4_WO)

__global__ void __launch_bounds__(256) cvt_all_kernel(
    const float* __restrict__ x,  __half* __restrict__ x16,
    const float* __restrict__ wq, __half* __restrict__ wq16,
    const float* __restrict__ wo, __half* __restrict__ wo16)
{
    long long i = (long long)blockIdx.x * 256 + threadIdx.x;
    const float* src;
    __half* dst;
    if (i < N4_X) {
        src = x; dst = x16;
    } else if (i < N4_X + N4_WQ) {
        i -= N4_X; src = wq; dst = wq16;
    } else {
        i -= N4_X + N4_WQ; src = wo; dst = wo16;
    }
    float4 v = ((const float4*)src)[i];
    uint2 o;
    o.x = h2pack(v.x, v.y);
    o.y = h2pack(v.z, v.w);
    ((uint2*)dst)[i] = o;
}

// =============================================================================
// launch
// =============================================================================
extern "C" void kernel_launch(void* const* d_in, const int* in_sizes, int n_in,
                              void* d_out, int out_size)
{
    (void)in_sizes; (void)n_in; (void)out_size;
    const float* x     = (const float*)d_in[0];   // [1, 2048, 2048]
    const float* w_qkv = (const float*)d_in[1];   // [6144, 2048]
    const float* w_out = (const float*)d_in[2];   // [2048, 2048]
    float* out = (float*)d_out;                   // [1, 2048, 2048]

    __half *x16, *wq16, *wo16, *q16, *k16, *vt16, *at16;
    float2* rope;
    cudaGetSymbolAddress((void**)&x16,  g_x16);
    cudaGetSymbolAddress((void**)&wq16, g_wq16);
    cudaGetSymbolAddress((void**)&wo16, g_wo16);
    cudaGetSymbolAddress((void**)&q16,  g_q16);
    cudaGetSymbolAddress((void**)&k16,  g_k16);
    cudaGetSymbolAddress((void**)&vt16, g_vt16);
    cudaGetSymbolAddress((void**)&at16, g_at16);
    cudaGetSymbolAddress((void**)&rope, g_rope);

    cudaFuncSetAttribute(gemm_tc_kernel,  cudaFuncAttributeMaxDynamicSharedMemorySize, GEMM_SMEM);
    cudaFuncSetAttribute(gemm_qkv_kernel, cudaFuncAttributeMaxDynamicSharedMemorySize, GEMM_SMEM);
    cudaFuncSetAttribute(flash_kernel,    cudaFuncAttributeMaxDynamicSharedMemorySize, FLASH_SMEM);

    // 0) rope table + fused fp32->fp16 conversions
    rope_tab_kernel<<<(S_LEN * 64) / 256, 256>>>(rope);
    cvt_all_kernel<<<(unsigned)((N4_ALL + 255) / 256), 256>>>(x, x16, w_qkv, wq16, w_out, wo16);

    // 1) fused QKV projection + RoPE + V transpose -> q16, k16, vt16
    {
        dim3 grid(E3 / 256, S_LEN / 128, 1);
        gemm_qkv_kernel<<<grid, 256, GEMM_SMEM>>>(x16, wq16, rope, q16, k16, vt16);
    }

    // 2) flash attention v2 -> at16 (128 CTAs, single wave)
    {
        dim3 grid(S_LEN / 256, N_HEADS, 1);
        flash_kernel<<<grid, 256, FLASH_SMEM>>>(q16, k16, vt16, at16);
    }

    // 3) out projection (fp32 out)
    {
        dim3 grid(D_MODEL / 256, S_LEN / 128, 1);
        gemm_tc_kernel<<<grid, 256, GEMM_SMEM>>>(at16, wo16, out,
                                                 D_MODEL, D_MODEL, D_MODEL, D_MODEL, 1.0f);
    }
}